// round 2
// baseline (speedup 1.0000x reference)
#include <cuda_runtime.h>
#include <math.h>

// Problem constants (from reference)
#define MAXN   524288
#define SPIN   1000
#define TRAINN 400000
#define ML_C   2.9086f
#define SL_C   1.898f

#define TILE   2048
#define SEQ_THREADS 128

// Scratch (no allocations allowed)
__device__ float  g_ol[MAXN];    // precomputed ol gate (depends only on u2)
__device__ float  g_c[MAXN];     // state entering each step
__device__ double g_acc[2];      // sum, sumsq for obsstd
__device__ float  g_par[12];
// g_par: 0=A2 1=B2 (exp2 coeffs for oo-sigmoid: exp(-z)=exp2(A2*c0+B2))
//        2=oo1 3=ol1 4=svm 5=thr 6=K(=thr*500) 7=AL 8=BL (ol-sigmoid coeffs)
//        9=obsstd

// ---------------------------------------------------------------------------
__global__ void k_setup(const float* pm, const float* ps,
                        const float* wr_yom, const float* wr_ylm,
                        const float* wr_yfm, const float* wr_yvm,
                        const float* b0_yom, const float* wb1p,
                        const float* b0_ylm, const float* wb2p,
                        const float* b0_yrm) {
    const float LOG2E = 1.4426950408889634f;
    float mo = pm[0], so = ps[0];
    float wb1 = wb1p[0], wb2 = wb2p[0];
    float eo = expf(wr_yom[0]);
    float el = expf(wr_ylm[0]);
    float ef = expf(wr_yfm[0]);
    float den = eo + el + ef;
    float oo1 = eo / den;
    float ol1 = el / den;
    float svm = 1.0f / (1.0f + expf(-wr_yvm[0]));
    float thr = expf(b0_yrm[0]);

    float a = wb1 / so;           // z_oo = b0_yom + (c0 - mo)*a
    g_par[0] = -LOG2E * a;
    g_par[1] = -LOG2E * (b0_yom[0] - mo * a);
    g_par[2] = oo1;
    g_par[3] = ol1;
    g_par[4] = svm;
    g_par[5] = thr;
    g_par[6] = thr * 500.0f;
    float al = wb2 / SL_C;        // z_ol = b0_ylm + (u2 - ML)*al
    g_par[7] = -LOG2E * al;
    g_par[8] = -LOG2E * (b0_ylm[0] - ML_C * al);
    g_acc[0] = 0.0;
    g_acc[1] = 0.0;
}

// ---------------------------------------------------------------------------
// Precompute ol[i] = ol1 * sigmoid(b0_ylm + (u2-ML)/SL*wb2)  (input-only gate)
__global__ void k_prepass(const float2* __restrict__ x, int n) {
    int i = blockIdx.x * blockDim.x + threadIdx.x;
    if (i >= n) return;
    float u2 = x[i].y;
    float t = fmaf(u2, g_par[7], g_par[8]);
    float e;
    asm("ex2.approx.f32 %0, %1;" : "=f"(e) : "f"(t));
    g_ol[i] = g_par[3] / (1.0f + e);
}

// ---------------------------------------------------------------------------
// obsstd reduction over y_obs[SPIN:TRAINN], double accumulation
__global__ void k_reduce(const float* __restrict__ y, int ny) {
    int hi = TRAINN < ny ? TRAINN : ny;
    int count = hi - SPIN;
    double s = 0.0, s2 = 0.0;
    for (int i = blockIdx.x * blockDim.x + threadIdx.x; i < count;
         i += gridDim.x * blockDim.x) {
        double v = (double)y[SPIN + i];
        s  += v;
        s2 += v * v;
    }
    #pragma unroll
    for (int o = 16; o; o >>= 1) {
        s  += __shfl_down_sync(0xFFFFFFFFu, s,  o);
        s2 += __shfl_down_sync(0xFFFFFFFFu, s2, o);
    }
    if ((threadIdx.x & 31) == 0) {
        atomicAdd(&g_acc[0], s);
        atomicAdd(&g_acc[1], s2);
    }
}

__global__ void k_finalize(int ny) {
    int hi = TRAINN < ny ? TRAINN : ny;
    double cnt = (double)(hi - SPIN);
    double var = (g_acc[1] - g_acc[0] * g_acc[0] / cnt) / (cnt - 1.0);
    g_par[9] = (float)sqrt(var > 0.0 ? var : 0.0);
}

// ---------------------------------------------------------------------------
// The sequential recurrence. One block; threads stage tiles into smem,
// lane 0 runs the scalar recurrence.
__global__ void __launch_bounds__(SEQ_THREADS, 1)
k_scan(const float2* __restrict__ x, int n, const int* __restrict__ tlp) {
    __shared__ float su1[TILE], su2[TILE], sol[TILE], sc[TILE];
    int tl = tlp[0];
    float A2  = g_par[0], B2 = g_par[1], oo1 = g_par[2];
    float svm = g_par[4], thr = g_par[5], K = g_par[6];
    float c = 0.0f;

    for (int base = 0; base < n; base += TILE) {
        int lim = n - base; if (lim > TILE) lim = TILE;
        for (int j = threadIdx.x; j < lim; j += SEQ_THREADS) {
            float2 xv = x[base + j];
            su1[j] = xv.x;
            su2[j] = xv.y;
            sol[j] = g_ol[base + j];
        }
        __syncthreads();
        if (threadIdx.x == 0) {
            float cl = c;
            #pragma unroll 4
            for (int j = 0; j < lim; j++) {
                int i = base + j;
                sc[j] = cl;                       // state ENTERING step i
                if (i >= tl) {
                    float c0 = cl;
                    float u1 = su1[j], u2 = su2[j], ol = sol[j];
                    // oo-sigmoid chain: exp(-z) = exp2(A2*c0 + B2)
                    float t = fmaf(c0, A2, B2);
                    float e;  asm("ex2.approx.f32 %0, %1;" : "=f"(e) : "f"(t));
                    float d = 1.0f + e;
                    float r;  asm("rcp.approx.f32 %0, %1;" : "=f"(r) : "f"(d));
                    // olc branch (parallel): q = u2/c0
                    float rc; asm("rcp.approx.f32 %0, %1;" : "=f"(rc) : "f"(c0));
                    float q = u2 * rc;
                    float olc = (c0 > 0.0f) ? fminf(ol, q) : ol;
                    // f = 1 - oo - olc,  oo = oo1*r
                    float f = fmaf(-oo1, r, 1.0f - olc);
                    // ov = min(svm*sign(c0/500 - thr), f)
                    float s = fmaf(c0, 0.002f, -thr);
                    float sg = (s > 0.0f) ? svm : ((s < 0.0f) ? -svm : 0.0f);
                    float ov = fminf(sg, f);
                    float absd = fabsf(c0 - K);
                    cl = fmaf(-ov, absd, fmaf(f, c0, u1));
                }
            }
            c = cl;
        }
        __syncthreads();
        for (int j = threadIdx.x; j < lim; j += SEQ_THREADS)
            g_c[base + j] = sc[j];
        __syncthreads();
    }
}

// ---------------------------------------------------------------------------
// Parallel epilogue: recompute gates from the state trajectory, write all
// 14 output columns.
// Layout: [h_n | c_n | l_n | lc_n | z | z | Goo | Gol | Golc | Gf |
//          h_nout(N,2 interleaved) | obs_std | Gov]
__global__ void k_out(const float2* __restrict__ x, int n,
                      const int* __restrict__ tlp, float* __restrict__ out) {
    int i = blockIdx.x * blockDim.x + threadIdx.x;
    if (i >= n) return;
    int tl = tlp[0];
    long long nn = n;
    if (i < tl) {
        out[i] = 0.0f;            out[nn + i] = 0.0f;
        out[2*nn + i] = 0.0f;     out[3*nn + i] = 0.0f;
        out[4*nn + i] = 0.0f;     out[5*nn + i] = 0.0f;
        out[6*nn + i] = 0.0f;     out[7*nn + i] = 0.0f;
        out[8*nn + i] = 0.0f;     out[9*nn + i] = 0.0f;
        out[10*nn + 2*(long long)i]     = 0.0f;
        out[10*nn + 2*(long long)i + 1] = 0.0f;
        out[12*nn + i] = 0.0f;    out[13*nn + i] = 0.0f;
        return;
    }
    float c0 = g_c[i];
    float u2 = x[i].y;
    float ol = g_ol[i];
    float thr = g_par[5], svm = g_par[4];

    float t = fmaf(c0, g_par[0], g_par[1]);
    float e;  asm("ex2.approx.f32 %0, %1;" : "=f"(e) : "f"(t));
    float oo = g_par[2] / (1.0f + e);
    float olc;
    if (c0 > 0.0f) olc = fminf(ol, u2 / c0); else olc = ol;
    float f = (1.0f - oo) - olc;
    float s = fmaf(c0, 0.002f, -thr);
    float sg = (s > 0.0f) ? svm : ((s < 0.0f) ? -svm : 0.0f);
    float ov = fminf(sg, f);
    float obss = g_par[9];
    float h = oo * c0;

    out[i]         = h;
    out[nn + i]    = c0;
    out[2*nn + i]  = ol * c0;
    out[3*nn + i]  = olc * c0;
    out[4*nn + i]  = 0.0f;
    out[5*nn + i]  = 0.0f;
    out[6*nn + i]  = oo;
    out[7*nn + i]  = ol;
    out[8*nn + i]  = olc;
    out[9*nn + i]  = f;
    out[10*nn + 2*(long long)i]     = h;
    out[10*nn + 2*(long long)i + 1] = obss;
    out[12*nn + i] = obss;
    out[13*nn + i] = ov;
}

// ---------------------------------------------------------------------------
extern "C" void kernel_launch(void* const* d_in, const int* in_sizes, int n_in,
                              void* d_out, int out_size) {
    const float2* x   = (const float2*)d_in[0];
    const float*  xf  = (const float*)d_in[0];
    const float*  y   = (const float*)d_in[1];
    const float*  pm  = (const float*)d_in[2];
    const float*  ps  = (const float*)d_in[3];
    const float*  wr_yom = (const float*)d_in[4];
    const float*  wr_ylm = (const float*)d_in[5];
    const float*  wr_yfm = (const float*)d_in[6];
    const float*  wr_yvm = (const float*)d_in[7];
    const float*  b0_yom = (const float*)d_in[8];
    const float*  wb1    = (const float*)d_in[9];
    const float*  b0_ylm = (const float*)d_in[10];
    const float*  wb2    = (const float*)d_in[11];
    const float*  b0_yrm = (const float*)d_in[12];
    const int*    tlp    = (const int*)d_in[14];   // time_lag
    float* out = (float*)d_out;
    (void)xf; (void)n_in; (void)out_size;

    int n  = in_sizes[0] / 2;
    if (n > MAXN) n = MAXN;
    int ny = in_sizes[1];

    k_setup<<<1, 1>>>(pm, ps, wr_yom, wr_ylm, wr_yfm, wr_yvm,
                      b0_yom, wb1, b0_ylm, wb2, b0_yrm);
    k_prepass<<<(n + 255) / 256, 256>>>(x, n);
    k_reduce<<<160, 256>>>(y, ny);
    k_finalize<<<1, 1>>>(ny);
    k_scan<<<1, SEQ_THREADS>>>(x, n, tlp);
    k_out<<<(n + 255) / 256, 256>>>(x, n, tlp, out);
}